// round 17
// baseline (speedup 1.0000x reference)
#include <cuda_runtime.h>
#include <cfloat>
#include <cstdint>

#define Bn 16
#define Cn 64
#define Nn 2048
#define On 64
#define Kn 20
#define CNT_TOT (16*2048*20)

// ---------------- scratch (static device globals; no runtime allocation) ----------------
__device__ float  g_D[(size_t)Bn*Nn*Nn];     // 256 MB neg_dist scratch
__device__ float  g_xx[Bn*Nn];               // squared norms
__device__ int    g_idx[Bn*Nn*Kn];           // top-K index sets (order arbitrary)
__device__ float  g_U[(size_t)Bn*Nn*On];     // U[b][m][o] = Wd . x  (o contiguous)
__device__ float  g_Bse[(size_t)Bn*Nn*On];   // (V-U)[b][n][o]
__device__ double g_sum[On], g_sumsq[On];
__device__ float  g_scale[On], g_shift[On];

// ---------------- kernel 0: zero the stats accumulators (graph replays!) ----------------
__global__ void k_zero() {
    int o = threadIdx.x;
    g_sum[o] = 0.0; g_sumsq[o] = 0.0;
}

// ---------------- kernel 1: xx[b,n] = sum_c x^2 ----------------
__global__ void k_xx(const float* __restrict__ x) {
    int id = blockIdx.x * blockDim.x + threadIdx.x;   // 0 .. B*N-1
    if (id >= Bn * Nn) return;
    int b = id / Nn, n = id % Nn;
    const float* xp = x + (size_t)b * Cn * Nn + n;
    float s = 0.f;
#pragma unroll
    for (int c = 0; c < Cn; c++) {
        float v = xp[(size_t)c * Nn];
        s = fmaf(v, v, s);
    }
    g_xx[id] = s;
}

// ---------------- kernel 2: neg_dist 128x128 tiles, 8x8 per thread ----------------
// Triangular grid (tm >= tn); mirror written via smem transpose.
__global__ void __launch_bounds__(256) k_gram(const float* __restrict__ x) {
    __shared__ __align__(16) float sh[64 * 132];   // As|Bs during compute, Ts after

    int t = blockIdx.x, b = blockIdx.y;
    int tm = (int)((sqrtf(8.f * t + 1.f) - 1.f) * 0.5f);
    while ((tm + 1) * (tm + 2) / 2 <= t) tm++;
    while (tm * (tm + 1) / 2 > t) tm--;
    int tn = t - tm * (tm + 1) / 2;

    int n0 = tn * 128, m0 = tm * 128;
    const float* xb = x + (size_t)b * Cn * Nn;
    int tid = threadIdx.x, tx = tid & 15, ty = tid >> 4;

    float* As = sh;            // [32][128]
    float* Bs = sh + 32 * 128; // [32][128]

    float acc[8][8] = {};

    for (int kc = 0; kc < 64; kc += 32) {
        __syncthreads();
#pragma unroll
        for (int i = 0; i < 4; i++) {
            int f = tid + 256 * i;          // float4 index over 1024
            int c = f >> 5, c4 = (f & 31) * 4;
            *(float4*)&As[c * 128 + c4] = *(const float4*)&xb[(size_t)(kc + c) * Nn + n0 + c4];
            *(float4*)&Bs[c * 128 + c4] = *(const float4*)&xb[(size_t)(kc + c) * Nn + m0 + c4];
        }
        __syncthreads();
#pragma unroll 4
        for (int c = 0; c < 32; c++) {
            float4 a0 = *(float4*)&As[c * 128 + ty * 4];
            float4 a1 = *(float4*)&As[c * 128 + 64 + ty * 4];
            float4 b0 = *(float4*)&Bs[c * 128 + tx * 4];
            float4 b1 = *(float4*)&Bs[c * 128 + 64 + tx * 4];
            float av[8] = {a0.x, a0.y, a0.z, a0.w, a1.x, a1.y, a1.z, a1.w};
            float bv[8] = {b0.x, b0.y, b0.z, b0.w, b1.x, b1.y, b1.z, b1.w};
#pragma unroll
            for (int i = 0; i < 8; i++)
#pragma unroll
                for (int j = 0; j < 8; j++)
                    acc[i][j] = fmaf(av[i], bv[j], acc[i][j]);
        }
    }

    float xn[8], xm[8];
#pragma unroll
    for (int i = 0; i < 4; i++) {
        xn[i]     = g_xx[b * Nn + n0 + ty * 4 + i];
        xn[4 + i] = g_xx[b * Nn + n0 + 64 + ty * 4 + i];
        xm[i]     = g_xx[b * Nn + m0 + tx * 4 + i];
        xm[4 + i] = g_xx[b * Nn + m0 + 64 + tx * 4 + i];
    }

    float vv[8][8];
#pragma unroll
    for (int i = 0; i < 8; i++)
#pragma unroll
        for (int j = 0; j < 8; j++)
            vv[i][j] = 2.f * acc[i][j] - xn[i] - xm[j];

    float* Db = g_D + (size_t)b * Nn * Nn;

    // direct store: D[n][m]
#pragma unroll
    for (int i = 0; i < 8; i++) {
        int nl = (i < 4) ? (ty * 4 + i) : (64 + ty * 4 + i - 4);
        *(float4*)&Db[(size_t)(n0 + nl) * Nn + m0 + tx * 4] =
            make_float4(vv[i][0], vv[i][1], vv[i][2], vv[i][3]);
        *(float4*)&Db[(size_t)(n0 + nl) * Nn + m0 + 64 + tx * 4] =
            make_float4(vv[i][4], vv[i][5], vv[i][6], vv[i][7]);
    }

    // mirror store: D[m][n] via smem transpose (two 64-col halves)
    if (tm != tn) {
        float* Ts = sh;                       // [64][132]
#pragma unroll
        for (int h = 0; h < 2; h++) {
            __syncthreads();
#pragma unroll
            for (int i = 0; i < 8; i++) {
                int nl = (i < 4) ? (ty * 4 + i) : (64 + ty * 4 + i - 4);
#pragma unroll
                for (int j = 0; j < 4; j++)
                    Ts[(tx * 4 + j) * 132 + nl] = vv[i][h * 4 + j];
            }
            __syncthreads();
#pragma unroll
            for (int q = 0; q < 8; q++) {
                int f = tid + 256 * q;        // over 64*32 float4
                int mc = f >> 5, n4 = (f & 31) * 4;
                float4 w = *(float4*)&Ts[mc * 132 + n4];
                *(float4*)&Db[(size_t)(m0 + h * 64 + mc) * Nn + n0 + n4] = w;
            }
        }
    }
}

// ---------------- kernel 3: top-K=20, ONE WARP PER ROW, zero block barriers ----------
// Lane holds 64 values (16 coalesced float4; element e = j*128 + lane*4 + q).
// thr = warp-min of per-lane maxes over ALL values -> count(>=thr) >= 32 by
// construction. Warp-private 256-bin histogram over [thr, 0] (monotone map),
// warp suffix scan, direct emit of bins above the threshold bin (only the SET
// matters downstream), exact (value desc, idx asc) rank inside the threshold
// bin -> identical set to stable top_k. Mass-tie pathology falls back to an
// eviction-free exact selection scan. All warp-synchronous.
__global__ void __launch_bounds__(256) k_topk3() {
    int tid = threadIdx.x, lane = tid & 31, warp = tid >> 5;
    int row = blockIdx.x * 8 + warp;
    const float4* d4 = (const float4*)(g_D + (size_t)row * Nn);

    __shared__ int   hist[8][257];
    __shared__ int   s_cnt[8], s_tb[8], s_win[8], s_kp[8];
    __shared__ float          cv[8][32];
    __shared__ unsigned short cix[8][32];

    float4 v[16];
#pragma unroll
    for (int j = 0; j < 16; j++) v[j] = d4[j * 32 + lane];   // MLP 16

#pragma unroll
    for (int j = 0; j < 8; j++) hist[warp][lane * 8 + j] = 0;
    if (lane == 0) { hist[warp][256] = 0; s_cnt[warp] = 0; s_tb[warp] = 0; }

    float lmax = -FLT_MAX;
#pragma unroll
    for (int j = 0; j < 16; j++)
        lmax = fmaxf(lmax, fmaxf(fmaxf(v[j].x, v[j].y), fmaxf(v[j].z, v[j].w)));
    float thr = lmax;
#pragma unroll
    for (int off = 16; off; off >>= 1)
        thr = fminf(thr, __shfl_xor_sync(0xffffffffu, thr, off));

    bool fb = (thr > -1e-20f);              // degenerate: many ~zero distances
    int* op = g_idx + row * Kn;

    if (!fb) {
        float scale = 255.f / (-thr);
        __syncwarp();
        // histogram of elements >= thr (~130 per row)
#pragma unroll
        for (int j = 0; j < 16; j++) {
            float vals[4] = {v[j].x, v[j].y, v[j].z, v[j].w};
#pragma unroll
            for (int q = 0; q < 4; q++) {
                if (vals[q] >= thr) {
                    int bb = (int)((vals[q] - thr) * scale);
                    bb = bb > 255 ? 255 : bb;
                    atomicAdd(&hist[warp][bb], 1);
                }
            }
        }
        __syncwarp();
        // suffix counts in place (8 bins/lane)
        int base = lane * 8, l[8], run = 0;
#pragma unroll
        for (int j = 7; j >= 0; j--) { run += hist[warp][base + j]; l[j] = run; }
        int tot = run, inc = tot;
#pragma unroll
        for (int off = 1; off < 32; off <<= 1) {
            int t = __shfl_down_sync(0xffffffffu, inc, off);
            if (lane + off < 32) inc += t;
        }
        int above = inc - tot;
#pragma unroll
        for (int j = 0; j < 8; j++) hist[warp][base + j] = l[j] + above;
        __syncwarp();
        // threshold bin: suffix >= K > next suffix (total >= 32 so it exists)
#pragma unroll
        for (int j = 0; j < 8; j++) {
            int bb = base + j;
            int cg = hist[warp][bb], cgn = hist[warp][bb + 1];
            if (cg >= Kn && cgn < Kn) { s_win[warp] = bb; s_kp[warp] = Kn - cgn; }
        }
        __syncwarp();
        int win = s_win[warp], kp = s_kp[warp];

        // direct emit (> win, set order arbitrary) + collect threshold bin
#pragma unroll
        for (int j = 0; j < 16; j++) {
            float vals[4] = {v[j].x, v[j].y, v[j].z, v[j].w};
#pragma unroll
            for (int q = 0; q < 4; q++) {
                if (vals[q] >= thr) {
                    int bb = (int)((vals[q] - thr) * scale);
                    bb = bb > 255 ? 255 : bb;
                    int e = j * 128 + lane * 4 + q;
                    if (bb > win) {
                        op[atomicAdd(&s_cnt[warp], 1)] = e;
                    } else if (bb == win) {
                        int p = atomicAdd(&s_tb[warp], 1);
                        if (p < 32) { cv[warp][p] = vals[q]; cix[warp][p] = (unsigned short)e; }
                    }
                }
            }
        }
        __syncwarp();
        int cc = s_tb[warp], bpos = s_cnt[warp];   // bpos == Kn - kp
        if (cc <= 32) {
            // exact rank in threshold bin by (value desc, idx asc); cc ~ 1-3
            for (int i = lane; i < cc; i += 32) {
                float vi = cv[warp][i]; int xi = cix[warp][i];
                int r = 0;
                for (int j = 0; j < cc; j++) {
                    float vj = cv[warp][j];
                    r += (vj > vi) || (vj == vi && cix[warp][j] < xi);
                }
                if (r < kp) op[bpos + r] = xi;
            }
            return;                                // warp-uniform
        }
        fb = true;                                 // fat threshold bin -> exact path
    }

    // exact fallback (rare): eviction-free selection by strict (value desc,
    // idx asc) order; no dynamic register indexing.
    float pv = FLT_MAX; int pi = -1;
    for (int k = 0; k < Kn; k++) {
        float bv = -FLT_MAX; int bi = 0x7fffffff;
#pragma unroll
        for (int j = 0; j < 16; j++) {
            float vals[4] = {v[j].x, v[j].y, v[j].z, v[j].w};
#pragma unroll
            for (int q = 0; q < 4; q++) {
                int e = j * 128 + lane * 4 + q;
                float vq = vals[q];
                bool lt_prev = (vq < pv) || (vq == pv && e > pi);
                if (lt_prev && (vq > bv || (vq == bv && e < bi))) { bv = vq; bi = e; }
            }
        }
#pragma unroll
        for (int off = 16; off; off >>= 1) {
            float ov = __shfl_down_sync(0xffffffffu, bv, off);
            int   oi = __shfl_down_sync(0xffffffffu, bi, off);
            if (ov > bv || (ov == bv && oi < bi)) { bv = ov; bi = oi; }
        }
        bv = __shfl_sync(0xffffffffu, bv, 0);
        bi = __shfl_sync(0xffffffffu, bi, 0);
        if (lane == 0) op[k] = bi;
        pv = bv; pi = bi;
    }
}

// ---------------- kernel 4: U = Wd.x , Bse = (Wc-Wd).x  (o-contiguous layout) -----------
__global__ void k_uv(const float* __restrict__ x, const float* __restrict__ W) {
    int b = blockIdx.y;
    int m0 = blockIdx.x * 64;
    __shared__ float Wd[64 * 64];   // [c][o]
    __shared__ float Wf[64 * 64];   // [c][o]  (Wc - Wd)
    __shared__ float xs[64 * 64];   // [c][m]
    int tid = threadIdx.x;
#pragma unroll
    for (int i = 0; i < 16; i++) {
        int id = tid + 256 * i;
        int o = id >> 6, c = id & 63;
        float wd = W[o * 128 + c];
        float wc = W[o * 128 + 64 + c];
        Wd[c * 64 + o] = wd;
        Wf[c * 64 + o] = wc - wd;
        xs[id] = x[(size_t)b * Cn * Nn + (size_t)(id >> 6) * Nn + m0 + (id & 63)];
    }
    __syncthreads();

    int o = tid & 63, mq = tid >> 6;
    float aU[16], aD[16];
#pragma unroll
    for (int t = 0; t < 16; t++) { aU[t] = 0.f; aD[t] = 0.f; }

    for (int c = 0; c < 64; c++) {
        float wu = Wd[c * 64 + o];
        float wf = Wf[c * 64 + o];
#pragma unroll
        for (int t = 0; t < 16; t++) {
            float xv = xs[c * 64 + mq + t * 4];   // broadcast within warp
            aU[t] = fmaf(wu, xv, aU[t]);
            aD[t] = fmaf(wf, xv, aD[t]);
        }
    }
#pragma unroll
    for (int t = 0; t < 16; t++) {
        int m = m0 + mq + t * 4;
        g_U  [((size_t)b * Nn + m) * On + o] = aU[t];
        g_Bse[((size_t)b * Nn + m) * On + o] = aD[t];
    }
}

// ---------------- kernel 5: per-channel sum / sumsq of y over (b,n,k) ----------------
__global__ void k_stats() {
    int b = blockIdx.y;
    int n0 = blockIdx.x * 128;
    int tid = threadIdx.x;
    int o = tid & 63, g = tid >> 6;
    float s = 0.f, s2 = 0.f;
    for (int j = 0; j < 32; j++) {
        int n = n0 + g * 32 + j;
        float bse = g_Bse[((size_t)b * Nn + n) * On + o];
        const int* ip = g_idx + (b * Nn + n) * Kn;
#pragma unroll
        for (int k = 0; k < Kn; k++) {
            int m = ip[k];
            float y = g_U[((size_t)b * Nn + m) * On + o] + bse;
            s += y;
            s2 = fmaf(y, y, s2);
        }
    }
    __shared__ float ss[4][64], ss2[4][64];
    ss[g][o] = s; ss2[g][o] = s2;
    __syncthreads();
    if (g == 0) {
        double ts = (double)ss[0][o] + (double)ss[1][o] + (double)ss[2][o] + (double)ss[3][o];
        double t2 = (double)ss2[0][o] + (double)ss2[1][o] + (double)ss2[2][o] + (double)ss2[3][o];
        atomicAdd(&g_sum[o], ts);
        atomicAdd(&g_sumsq[o], t2);
    }
}

// ---------------- kernel 6: finalize BN affine ----------------
__global__ void k_fin(const float* __restrict__ gamma, const float* __restrict__ beta) {
    int o = threadIdx.x;
    double mean = g_sum[o] / (double)CNT_TOT;
    double var  = g_sumsq[o] / (double)CNT_TOT - mean * mean;
    float sc = gamma[o] * rsqrtf((float)var + 1e-5f);
    g_scale[o] = sc;
    g_shift[o] = beta[o] - (float)mean * sc;
}

// ---------------- kernel 7: normalize + leaky relu + max over k -> out[b][o][n] --------
__global__ void k_out(float* __restrict__ out) {
    int b = blockIdx.y;
    int n0 = blockIdx.x * 32;
    int tid = threadIdx.x;
    int o = tid & 63, nq = tid >> 6;
    __shared__ float sm[64 * 33];
    float sc = g_scale[o], sh = g_shift[o];
    for (int j = 0; j < 8; j++) {
        int nl = nq * 8 + j;
        int n = n0 + nl;
        float bse = g_Bse[((size_t)b * Nn + n) * On + o];
        const int* ip = g_idx + (b * Nn + n) * Kn;
        float mx = -FLT_MAX;
#pragma unroll
        for (int k = 0; k < Kn; k++) {
            int m = ip[k];
            float y  = g_U[((size_t)b * Nn + m) * On + o] + bse;
            float yn = fmaf(y, sc, sh);
            float a  = (yn >= 0.f) ? yn : 0.2f * yn;
            mx = fmaxf(mx, a);
        }
        sm[o * 33 + nl] = mx;
    }
    __syncthreads();
    int nl2 = tid & 31, og = tid >> 5;
#pragma unroll
    for (int j = 0; j < 8; j++) {
        int o2 = og * 8 + j;
        out[((size_t)b * On + o2) * Nn + n0 + nl2] = sm[o2 * 33 + nl2];
    }
}

// ---------------- launch ----------------
extern "C" void kernel_launch(void* const* d_in, const int* in_sizes, int n_in,
                              void* d_out, int out_size) {
    const float* x     = (const float*)d_in[0];
    const float* W     = (const float*)d_in[1];
    const float* gamma = (const float*)d_in[2];
    const float* beta  = (const float*)d_in[3];
    float* out = (float*)d_out;

    k_zero<<<1, 64>>>();
    k_xx<<<(Bn * Nn) / 256, 256>>>(x);

    dim3 gg(136, 16);                 // triangular tile set, 128x128 tiles
    k_gram<<<gg, 256>>>(x);

    k_topk3<<<(Bn * Nn) / 8, 256>>>();

    dim3 guv(Nn / 64, Bn);
    k_uv<<<guv, 256>>>(x, W);

    dim3 gst(16, Bn);
    k_stats<<<gst, 256>>>();

    k_fin<<<1, 64>>>(gamma, beta);

    dim3 go(Nn / 32, Bn);
    k_out<<<go, 256>>>(out);
}